// round 8
// baseline (speedup 1.0000x reference)
#include <cuda_runtime.h>
#include <cstdint>

#define NN 100000
#define EE 1600000
#define RR 6
#define CIN 8
#define COUT 16
#define CHUNK 512

__device__ int    g_counts[NN];
__device__ int    g_rowstart[NN + 1];
__device__ int    g_cursor[NN];
__device__ int    g_src[EE];
__device__ int    g_dst[EE];
__device__ float4 g_payload[EE * 4];      // 64B per edge: sten(12f) + src + pad
__device__ int    g_bsum[256];
__device__ int    g_boff[256];
__device__ float2 g_phase[CIN * COUT];
__device__ int    g_is64;

// ---------------------------------------------------------------------------
// K1: detect int64-vs-int32 edges, zero histogram, precompute phase
__global__ void k_init(const float* __restrict__ offset,
                       const unsigned int* __restrict__ words, int n) {
    int i = blockIdx.x * blockDim.x + threadIdx.x;
    if (i == 0) {
        // int64 node ids < 2^31 -> all high words zero; int32 -> odd words are ids
        int any = 0;
        for (int k = 1; k < 512; k += 2) any |= (words[k] != 0u);
        g_is64 = any ? 0 : 1;
    }
    if (i < CIN * COUT) {
        float o = offset[i];
        g_phase[i] = make_float2(cosf(o), sinf(o));
    }
    if (i < n) g_counts[i] = 0;
}

// K2: decode edges once to int32 + histogram of destination degrees
__global__ void k_hist(const char* __restrict__ edges, int E) {
    int e = blockIdx.x * blockDim.x + threadIdx.x;
    if (e >= E) return;
    int src, dst;
    if (g_is64) {
        longlong2 v = ((const longlong2*)edges)[e];
        src = (int)v.x; dst = (int)v.y;
    } else {
        int2 v = ((const int2*)edges)[e];
        src = v.x; dst = v.y;
    }
    g_src[e] = src;
    g_dst[e] = dst;
    atomicAdd(&g_counts[dst], 1);
}

// K3a: per-block scan of CHUNK=512 counts (128 threads x 4), shuffle-based
__global__ void k_scan1(int n) {
    __shared__ int ws[4];
    int b = blockIdx.x, t = threadIdx.x;
    int base = b * CHUNK + t * 4;
    int v0 = 0, v1 = 0, v2 = 0, v3 = 0;
    if (base + 0 < n) v0 = g_counts[base + 0];
    if (base + 1 < n) v1 = g_counts[base + 1];
    if (base + 2 < n) v2 = g_counts[base + 2];
    if (base + 3 < n) v3 = g_counts[base + 3];
    int tot = v0 + v1 + v2 + v3;
    int lane = t & 31, wid = t >> 5;
    int s = tot;
#pragma unroll
    for (int off = 1; off < 32; off <<= 1) {
        int u = __shfl_up_sync(0xffffffffu, s, off);
        if (lane >= off) s += u;
    }
    if (lane == 31) ws[wid] = s;
    __syncthreads();
    int add = 0;
#pragma unroll
    for (int w = 0; w < 3; w++) if (w < wid) add += ws[w];
    int run = add + s - tot;  // exclusive prefix within block
    if (base + 0 < n) { g_rowstart[base + 0] = run; run += v0; }
    if (base + 1 < n) { g_rowstart[base + 1] = run; run += v1; }
    if (base + 2 < n) { g_rowstart[base + 2] = run; run += v2; }
    if (base + 3 < n) { g_rowstart[base + 3] = run; run += v3; }
    if (t == 127) g_bsum[b] = add + s;  // block total
}

// K3b: scan the (<=256) block sums
__global__ void k_scan2(int nb) {
    __shared__ int ws[8];
    int t = threadIdx.x;
    int v = (t < nb) ? g_bsum[t] : 0;
    int lane = t & 31, wid = t >> 5;
    int s = v;
#pragma unroll
    for (int off = 1; off < 32; off <<= 1) {
        int u = __shfl_up_sync(0xffffffffu, s, off);
        if (lane >= off) s += u;
    }
    if (lane == 31) ws[wid] = s;
    __syncthreads();
    int add = 0;
#pragma unroll
    for (int w = 0; w < 7; w++) if (w < wid) add += ws[w];
    if (t < nb) g_boff[t] = add + s - v;  // exclusive
}

// K3c: add block offsets, init cursor, terminate rowstart
__global__ void k_scan3(int n, int E) {
    int i = blockIdx.x * blockDim.x + threadIdx.x;
    if (i < n) {
        int v = g_rowstart[i] + g_boff[i / CHUNK];
        g_rowstart[i] = v;
        g_cursor[i] = v;
    }
    if (i == 0) g_rowstart[n] = E;
}

// K4: scatter full edge payload (sten + src, 64B sector-aligned) into
// dst-sorted order. Random writes are fire-and-forget, fully-covered sectors.
__global__ void k_payload(const float* __restrict__ sten, int E) {
    int e = blockIdx.x * blockDim.x + threadIdx.x;
    if (e >= E) return;
    const float4* s4 = (const float4*)(sten + (size_t)e * 12);
    float4 s0 = s4[0], s1 = s4[1], s2 = s4[2];
    int dst = g_dst[e];
    int src = g_src[e];
    int pos = atomicAdd(&g_cursor[dst], 1);
    float4* p = &g_payload[(size_t)pos * 4];
    p[0] = s0;
    p[1] = s1;
    p[2] = s2;
    p[3] = make_float4(__int_as_float(src), 0.f, 0.f, 0.f);
}

__device__ __forceinline__ void accum(float4 s0, float4 s1, float4 s2,
                                      float4 xa, float4 xb,
                                      float* ar, float* ai) {
    float sr[RR]  = {s0.x, s0.z, s1.x, s1.z, s2.x, s2.z};
    float si[RR]  = {s0.y, s0.w, s1.y, s1.w, s2.y, s2.w};
    float xv[CIN] = {xa.x, xa.y, xa.z, xa.w, xb.x, xb.y, xb.z, xb.w};
#pragma unroll
    for (int r = 0; r < RR; r++) {
#pragma unroll
        for (int c = 0; c < CIN; c++) {
            ar[r * CIN + c] += sr[r] * xv[c];
            ai[r * CIN + c] += si[r] * xv[c];
        }
    }
}

// K5: per-node streaming aggregation + factored complex contraction + gate
__global__ void __launch_bounds__(128)
k_node(const float* __restrict__ x, const float* __restrict__ weight,
       const float* __restrict__ bias, float* __restrict__ out, int n_nodes) {
    __shared__ float  sw[RR * CIN * COUT];
    __shared__ float2 sp[CIN * COUT];
    __shared__ float  sb[COUT];
    int t = threadIdx.x;
    for (int i = t; i < RR * CIN * COUT; i += 128) sw[i] = weight[i];
    sp[t] = g_phase[t];
    if (t < COUT) sb[t] = bias[t];
    __syncthreads();

    int n = blockIdx.x * 128 + t;
    if (n >= n_nodes) return;

    float ar[RR * CIN], ai[RR * CIN];
#pragma unroll
    for (int k = 0; k < RR * CIN; k++) { ar[k] = 0.f; ai[k] = 0.f; }

    int beg = g_rowstart[n];
    int end = g_rowstart[n + 1];

    int i = beg;
    // unroll-2: two independent payload reads + two independent x gathers
    for (; i + 2 <= end; i += 2) {
        const float4* p = &g_payload[(size_t)i * 4];
        float4 a0 = p[0], a1 = p[1], a2 = p[2], a3 = p[3];
        float4 b0 = p[4], b1 = p[5], b2 = p[6], b3 = p[7];
        int srcA = __float_as_int(a3.x);
        int srcB = __float_as_int(b3.x);
        const float4* xpa = (const float4*)(x + (size_t)srcA * CIN);
        const float4* xpb = (const float4*)(x + (size_t)srcB * CIN);
        float4 xa0 = xpa[0], xa1 = xpa[1];
        float4 xb0 = xpb[0], xb1 = xpb[1];
        accum(a0, a1, a2, xa0, xa1, ar, ai);
        accum(b0, b1, b2, xb0, xb1, ar, ai);
    }
    if (i < end) {
        const float4* p = &g_payload[(size_t)i * 4];
        float4 a0 = p[0], a1 = p[1], a2 = p[2], a3 = p[3];
        int srcA = __float_as_int(a3.x);
        const float4* xpa = (const float4*)(x + (size_t)srcA * CIN);
        accum(a0, a1, a2, xpa[0], xpa[1], ar, ai);
    }

    // y[o] = sum_c phase[c,o] * (sum_r agg[r,c] * w[r,c,o]); magnitude gate
    float2* o2 = (float2*)out;
#pragma unroll 4
    for (int o = 0; o < COUT; o++) {
        float yr = 0.f, yi = 0.f;
#pragma unroll
        for (int c = 0; c < CIN; c++) {
            float tr = 0.f, ti = 0.f;
#pragma unroll
            for (int r = 0; r < RR; r++) {
                float w = sw[(r * CIN + c) * COUT + o];
                tr += ar[r * CIN + c] * w;
                ti += ai[r * CIN + c] * w;
            }
            float2 ph = sp[c * COUT + o];
            yr += tr * ph.x - ti * ph.y;
            yi += tr * ph.y + ti * ph.x;
        }
        float mag = sqrtf(yr * yr + yi * yi);
        float sc = fmaxf(mag + sb[o], 0.f) / (mag + 1e-8f);
        o2[(size_t)n * COUT + o] = make_float2(yr * sc, yi * sc);
    }
}

extern "C" void kernel_launch(void* const* d_in, const int* in_sizes, int n_in,
                              void* d_out, int out_size) {
    const float* x      = (const float*)d_in[0];
    const char*  edges  = (const char*)d_in[1];
    const float* sten   = (const float*)d_in[2];
    const float* weight = (const float*)d_in[3];
    const float* offset = (const float*)d_in[4];
    const float* bias   = (const float*)d_in[5];
    float*       out    = (float*)d_out;

    int E = in_sizes[1] / 2;
    int n = in_sizes[0] / CIN;

    k_init<<<(n + 255) / 256, 256>>>(offset, (const unsigned int*)edges, n);
    k_hist<<<(E + 255) / 256, 256>>>(edges, E);
    int nb = (n + CHUNK - 1) / CHUNK;
    k_scan1<<<nb, 128>>>(n);
    k_scan2<<<1, 256>>>(nb);
    k_scan3<<<(n + 255) / 256, 256>>>(n, E);
    k_payload<<<(E + 255) / 256, 256>>>(sten, E);
    k_node<<<(n + 127) / 128, 128>>>(x, weight, bias, out, n);
}

// round 10
// speedup vs baseline: 1.1092x; 1.1092x over previous
#include <cuda_runtime.h>
#include <cstdint>

#define NN 100000
#define EE 1600000
#define RR 6
#define CIN 8
#define COUT 16
#define CHUNK 512

__device__ int    g_counts[NN];
__device__ int    g_rowstart[NN + 1];
__device__ int    g_cursor[NN];
__device__ int2   g_sd[EE];        // decoded (src, dst) int32
__device__ int2   g_pp[EE];        // dst-sorted (src, edge_id)
__device__ int    g_bsum[256];
__device__ int    g_boff[256];
__device__ float2 g_phase[CIN * COUT];
__device__ int    g_is64;

// ---------------------------------------------------------------------------
// K1: detect int64-vs-int32 edges, zero histogram, precompute phase
__global__ void k_init(const float* __restrict__ offset,
                       const unsigned int* __restrict__ words, int n) {
    int i = blockIdx.x * blockDim.x + threadIdx.x;
    if (i == 0) {
        // int64 ids < 2^31 -> all high words zero; int32 -> odd words are ids
        int any = 0;
        for (int k = 1; k < 512; k += 2) any |= (words[k] != 0u);
        g_is64 = any ? 0 : 1;
    }
    if (i < CIN * COUT) {
        float o = offset[i];
        g_phase[i] = make_float2(cosf(o), sinf(o));
    }
    if (i < n) g_counts[i] = 0;
}

// K2: decode edges once to int2 + histogram of destination degrees
__global__ void k_hist(const char* __restrict__ edges, int E) {
    int e = blockIdx.x * blockDim.x + threadIdx.x;
    if (e >= E) return;
    int src, dst;
    if (g_is64) {
        longlong2 v = ((const longlong2*)edges)[e];
        src = (int)v.x; dst = (int)v.y;
    } else {
        int2 v = ((const int2*)edges)[e];
        src = v.x; dst = v.y;
    }
    g_sd[e] = make_int2(src, dst);
    atomicAdd(&g_counts[dst], 1);
}

// K3a: per-block scan of CHUNK=512 counts (128 threads x 4), shuffle-based
__global__ void k_scan1(int n) {
    __shared__ int ws[4];
    int b = blockIdx.x, t = threadIdx.x;
    int base = b * CHUNK + t * 4;
    int v0 = 0, v1 = 0, v2 = 0, v3 = 0;
    if (base + 0 < n) v0 = g_counts[base + 0];
    if (base + 1 < n) v1 = g_counts[base + 1];
    if (base + 2 < n) v2 = g_counts[base + 2];
    if (base + 3 < n) v3 = g_counts[base + 3];
    int tot = v0 + v1 + v2 + v3;
    int lane = t & 31, wid = t >> 5;
    int s = tot;
#pragma unroll
    for (int off = 1; off < 32; off <<= 1) {
        int u = __shfl_up_sync(0xffffffffu, s, off);
        if (lane >= off) s += u;
    }
    if (lane == 31) ws[wid] = s;
    __syncthreads();
    int add = 0;
#pragma unroll
    for (int w = 0; w < 3; w++) if (w < wid) add += ws[w];
    int run = add + s - tot;  // exclusive prefix within block
    if (base + 0 < n) { g_rowstart[base + 0] = run; run += v0; }
    if (base + 1 < n) { g_rowstart[base + 1] = run; run += v1; }
    if (base + 2 < n) { g_rowstart[base + 2] = run; run += v2; }
    if (base + 3 < n) { g_rowstart[base + 3] = run; run += v3; }
    if (t == 127) g_bsum[b] = add + s;  // block total
}

// K3b: scan the (<=256) block sums
__global__ void k_scan2(int nb) {
    __shared__ int ws[8];
    int t = threadIdx.x;
    int v = (t < nb) ? g_bsum[t] : 0;
    int lane = t & 31, wid = t >> 5;
    int s = v;
#pragma unroll
    for (int off = 1; off < 32; off <<= 1) {
        int u = __shfl_up_sync(0xffffffffu, s, off);
        if (lane >= off) s += u;
    }
    if (lane == 31) ws[wid] = s;
    __syncthreads();
    int add = 0;
#pragma unroll
    for (int w = 0; w < 7; w++) if (w < wid) add += ws[w];
    if (t < nb) g_boff[t] = add + s - v;  // exclusive
}

// K3c: add block offsets, init cursor, terminate rowstart
__global__ void k_scan3(int n, int E) {
    int i = blockIdx.x * blockDim.x + threadIdx.x;
    if (i < n) {
        int v = g_rowstart[i] + g_boff[i / CHUNK];
        g_rowstart[i] = v;
        g_cursor[i] = v;
    }
    if (i == 0) g_rowstart[n] = E;
}

// K4: scatter packed (src, edge) 8B into dst-sorted order (one ST.64 each)
__global__ void k_scatter(int E) {
    int e = blockIdx.x * blockDim.x + threadIdx.x;
    if (e >= E) return;
    int2 sd = g_sd[e];
    int pos = atomicAdd(&g_cursor[sd.y], 1);
    g_pp[pos] = make_int2(sd.x, e);
}

__device__ __forceinline__ void accum(float4 s0, float4 s1, float4 s2,
                                      float4 xa, float4 xb,
                                      float* ar, float* ai) {
    float sr[RR]  = {s0.x, s0.z, s1.x, s1.z, s2.x, s2.z};
    float si[RR]  = {s0.y, s0.w, s1.y, s1.w, s2.y, s2.w};
    float xv[CIN] = {xa.x, xa.y, xa.z, xa.w, xb.x, xb.y, xb.z, xb.w};
#pragma unroll
    for (int r = 0; r < RR; r++) {
#pragma unroll
        for (int c = 0; c < CIN; c++) {
            ar[r * CIN + c] += sr[r] * xv[c];
            ai[r * CIN + c] += si[r] * xv[c];
        }
    }
}

// K5: 2 threads per node. Lane pair splits the edge run (2x MLP, half the
// warp imbalance), xor-shfl merges the 96 accumulators, epilogue split
// 8 outputs per lane.
__global__ void __launch_bounds__(256)
k_node(const float* __restrict__ x, const float* __restrict__ sten,
       const float* __restrict__ weight, const float* __restrict__ bias,
       float* __restrict__ out, int n_nodes) {
    __shared__ float  sw[RR * CIN * COUT];
    __shared__ float2 sp[CIN * COUT];
    __shared__ float  sb[COUT];
    int t = threadIdx.x;
    for (int i = t; i < RR * CIN * COUT; i += 256) sw[i] = weight[i];
    if (t < CIN * COUT) sp[t] = g_phase[t];
    if (t < COUT) sb[t] = bias[t];
    __syncthreads();

    int n    = blockIdx.x * 128 + (t >> 1);
    int half = t & 1;
    bool valid = (n < n_nodes);

    int beg = 0, end = 0;
    if (valid) { beg = g_rowstart[n]; end = g_rowstart[n + 1]; }
    int mid = beg + ((end - beg + 1) >> 1);
    int h0 = half ? mid : beg;
    int h1 = half ? end : mid;

    float ar[RR * CIN], ai[RR * CIN];
#pragma unroll
    for (int k = 0; k < RR * CIN; k++) { ar[k] = 0.f; ai[k] = 0.f; }

    int i = h0;
    for (; i + 2 <= h1; i += 2) {
        int2 p0 = g_pp[i];
        int2 p1 = g_pp[i + 1];
        const float4* sA = (const float4*)(sten + (size_t)p0.y * 12);
        const float4* sB = (const float4*)(sten + (size_t)p1.y * 12);
        float4 a0 = sA[0], a1 = sA[1], a2 = sA[2];
        float4 b0 = sB[0], b1 = sB[1], b2 = sB[2];
        const float4* xA = (const float4*)(x + (size_t)p0.x * CIN);
        const float4* xB = (const float4*)(x + (size_t)p1.x * CIN);
        float4 xa0 = xA[0], xa1 = xA[1];
        float4 xb0 = xB[0], xb1 = xB[1];
        accum(a0, a1, a2, xa0, xa1, ar, ai);
        accum(b0, b1, b2, xb0, xb1, ar, ai);
    }
    if (i < h1) {
        int2 p0 = g_pp[i];
        const float4* sA = (const float4*)(sten + (size_t)p0.y * 12);
        float4 a0 = sA[0], a1 = sA[1], a2 = sA[2];
        const float4* xA = (const float4*)(x + (size_t)p0.x * CIN);
        accum(a0, a1, a2, xA[0], xA[1], ar, ai);
    }

    // merge the lane pair (both lanes end with the full sum)
#pragma unroll
    for (int k = 0; k < RR * CIN; k++) {
        ar[k] += __shfl_xor_sync(0xffffffffu, ar[k], 1);
        ai[k] += __shfl_xor_sync(0xffffffffu, ai[k], 1);
    }

    if (!valid) return;

    // y[o] = sum_c phase[c,o] * (sum_r agg[r,c] * w[r,c,o]); magnitude gate
    // even lane: o = 0..7, odd lane: o = 8..15
    float2* o2 = (float2*)out;
    int obeg = half * 8;
#pragma unroll
    for (int oo = 0; oo < 8; oo++) {
        int o = obeg + oo;
        float yr = 0.f, yi = 0.f;
#pragma unroll
        for (int c = 0; c < CIN; c++) {
            float tr = 0.f, ti = 0.f;
#pragma unroll
            for (int r = 0; r < RR; r++) {
                float w = sw[(r * CIN + c) * COUT + o];
                tr += ar[r * CIN + c] * w;
                ti += ai[r * CIN + c] * w;
            }
            float2 ph = sp[c * COUT + o];
            yr += tr * ph.x - ti * ph.y;
            yi += tr * ph.y + ti * ph.x;
        }
        float mag = sqrtf(yr * yr + yi * yi);
        float sc = fmaxf(mag + sb[o], 0.f) / (mag + 1e-8f);
        o2[(size_t)n * COUT + o] = make_float2(yr * sc, yi * sc);
    }
}

extern "C" void kernel_launch(void* const* d_in, const int* in_sizes, int n_in,
                              void* d_out, int out_size) {
    const float* x      = (const float*)d_in[0];
    const char*  edges  = (const char*)d_in[1];
    const float* sten   = (const float*)d_in[2];
    const float* weight = (const float*)d_in[3];
    const float* offset = (const float*)d_in[4];
    const float* bias   = (const float*)d_in[5];
    float*       out    = (float*)d_out;

    int E = in_sizes[1] / 2;
    int n = in_sizes[0] / CIN;

    k_init<<<(n + 255) / 256, 256>>>(offset, (const unsigned int*)edges, n);
    k_hist<<<(E + 255) / 256, 256>>>(edges, E);
    int nb = (n + CHUNK - 1) / CHUNK;
    k_scan1<<<nb, 128>>>(n);
    k_scan2<<<1, 256>>>(nb);
    k_scan3<<<(n + 255) / 256, 256>>>(n, E);
    k_scatter<<<(E + 255) / 256, 256>>>(E);
    k_node<<<(n + 127) / 128, 256>>>(x, sten, weight, bias, out, n);
}

// round 13
// speedup vs baseline: 1.3764x; 1.2409x over previous
#include <cuda_runtime.h>
#include <cstdint>

#define NN 100000
#define EE 1600000
#define RR 6
#define CIN 8
#define COUT 16
#define CHUNK 1024

__device__ int    g_counts[NN];
__device__ int    g_rowstart[NN + 1];
__device__ int    g_cursor[NN];
__device__ int2   g_sd[EE];        // decoded (src, dst) int32
__device__ int2   g_pp[EE];        // dst-sorted (src, edge_id)
__device__ int    g_bsum[128];
__device__ float2 g_phase[CIN * COUT];
__device__ int    g_is64;

// ---------------------------------------------------------------------------
// K1: detect int64-vs-int32 edges, zero histogram, precompute phase
__global__ void k_init(const float* __restrict__ offset,
                       const unsigned int* __restrict__ words, int n) {
    int i = blockIdx.x * blockDim.x + threadIdx.x;
    if (i == 0) {
        int any = 0;
        for (int k = 1; k < 512; k += 2) any |= (words[k] != 0u);
        g_is64 = any ? 0 : 1;
    }
    if (i < CIN * COUT) {
        float o = offset[i];
        g_phase[i] = make_float2(cosf(o), sinf(o));
    }
    if (i < n) g_counts[i] = 0;
}

// K2: decode edges once to int2 + histogram of destination degrees
__global__ void k_hist(const char* __restrict__ edges, int E) {
    int e = blockIdx.x * blockDim.x + threadIdx.x;
    if (e >= E) return;
    int src, dst;
    if (g_is64) {
        longlong2 v = ((const longlong2*)edges)[e];
        src = (int)v.x; dst = (int)v.y;
    } else {
        int2 v = ((const int2*)edges)[e];
        src = v.x; dst = v.y;
    }
    g_sd[e] = make_int2(src, dst);
    atomicAdd(&g_counts[dst], 1);
}

// K3a: per-block scan of CHUNK=1024 counts (256 threads x 4), shuffle-based
__global__ void k_scan1(int n) {
    __shared__ int ws[8];
    int b = blockIdx.x, t = threadIdx.x;
    int base = b * CHUNK + t * 4;
    int v0 = 0, v1 = 0, v2 = 0, v3 = 0;
    if (base + 0 < n) v0 = g_counts[base + 0];
    if (base + 1 < n) v1 = g_counts[base + 1];
    if (base + 2 < n) v2 = g_counts[base + 2];
    if (base + 3 < n) v3 = g_counts[base + 3];
    int tot = v0 + v1 + v2 + v3;
    int lane = t & 31, wid = t >> 5;
    int s = tot;
#pragma unroll
    for (int off = 1; off < 32; off <<= 1) {
        int u = __shfl_up_sync(0xffffffffu, s, off);
        if (lane >= off) s += u;
    }
    if (lane == 31) ws[wid] = s;
    __syncthreads();
    int add = 0;
#pragma unroll
    for (int w = 0; w < 7; w++) if (w < wid) add += ws[w];
    int run = add + s - tot;  // exclusive prefix within block
    if (base + 0 < n) { g_rowstart[base + 0] = run; run += v0; }
    if (base + 1 < n) { g_rowstart[base + 1] = run; run += v1; }
    if (base + 2 < n) { g_rowstart[base + 2] = run; run += v2; }
    if (base + 3 < n) { g_rowstart[base + 3] = run; run += v3; }
    if (t == 255) g_bsum[b] = add + s;  // block total
}

// K3b: fused block-offset apply. Each block spans 256 indices -> exactly one
// chunk (CHUNK=1024, 256 | 1024). Warp 0 reduces bsum[0..cid), then all
// threads add it, init cursor, and terminate rowstart.
__global__ void k_scan2(int n, int E, int nb) {
    __shared__ int s_off;
    int t = threadIdx.x;
    int i0 = blockIdx.x * 256;
    int cid = i0 / CHUNK;
    if (t < 32) {
        int acc = 0;
        for (int j = t; j < cid; j += 32) acc += g_bsum[j];
#pragma unroll
        for (int off = 16; off > 0; off >>= 1)
            acc += __shfl_down_sync(0xffffffffu, acc, off);
        if (t == 0) s_off = acc;
    }
    __syncthreads();
    int i = i0 + t;
    if (i < n) {
        int v = g_rowstart[i] + s_off;
        g_rowstart[i] = v;
        g_cursor[i] = v;
    }
    if (i == 0) g_rowstart[n] = E;
}

// K4: scatter packed (src, edge) 8B into dst-sorted order
__global__ void k_scatter(int E) {
    int e = blockIdx.x * blockDim.x + threadIdx.x;
    if (e >= E) return;
    int2 sd = g_sd[e];
    int pos = atomicAdd(&g_cursor[sd.y], 1);
    g_pp[pos] = make_int2(sd.x, e);
}

__device__ __forceinline__ void accum(float4 s0, float4 s1, float4 s2,
                                      float4 xa, float4 xb,
                                      float* ar, float* ai) {
    float sr[RR]  = {s0.x, s0.z, s1.x, s1.z, s2.x, s2.z};
    float si[RR]  = {s0.y, s0.w, s1.y, s1.w, s2.y, s2.w};
    float xv[CIN] = {xa.x, xa.y, xa.z, xa.w, xb.x, xb.y, xb.z, xb.w};
#pragma unroll
    for (int r = 0; r < RR; r++) {
#pragma unroll
        for (int c = 0; c < CIN; c++) {
            ar[r * CIN + c] += sr[r] * xv[c];
            ai[r * CIN + c] += si[r] * xv[c];
        }
    }
}

// K5: one thread per node, unroll-4 (4 independent pp/sten/x load groups in
// flight), 128 threads/block for a 512-reg budget (no spills).
__global__ void __launch_bounds__(128)
k_node(const float* __restrict__ x, const float* __restrict__ sten,
       const float* __restrict__ weight, const float* __restrict__ bias,
       float* __restrict__ out, int n_nodes) {
    __shared__ float  sw[RR * CIN * COUT];
    __shared__ float2 sp[CIN * COUT];
    __shared__ float  sb[COUT];
    int t = threadIdx.x;
    for (int i = t; i < RR * CIN * COUT; i += 128) sw[i] = weight[i];
    sp[t] = g_phase[t];
    if (t < COUT) sb[t] = bias[t];
    __syncthreads();

    int n = blockIdx.x * 128 + t;
    if (n >= n_nodes) return;

    float ar[RR * CIN], ai[RR * CIN];
#pragma unroll
    for (int k = 0; k < RR * CIN; k++) { ar[k] = 0.f; ai[k] = 0.f; }

    int beg = g_rowstart[n];
    int end = g_rowstart[n + 1];

    int i = beg;
    for (; i + 4 <= end; i += 4) {
        // batch the index loads first (4 independent)
        int2 p0 = g_pp[i + 0];
        int2 p1 = g_pp[i + 1];
        int2 p2 = g_pp[i + 2];
        int2 p3 = g_pp[i + 3];
        const float4* sA = (const float4*)(sten + (size_t)p0.y * 12);
        const float4* sB = (const float4*)(sten + (size_t)p1.y * 12);
        const float4* sC = (const float4*)(sten + (size_t)p2.y * 12);
        const float4* sD = (const float4*)(sten + (size_t)p3.y * 12);
        const float4* xA = (const float4*)(x + (size_t)p0.x * CIN);
        const float4* xB = (const float4*)(x + (size_t)p1.x * CIN);
        const float4* xC = (const float4*)(x + (size_t)p2.x * CIN);
        const float4* xD = (const float4*)(x + (size_t)p3.x * CIN);
        // issue all 20 wide loads before consuming any
        float4 a0 = sA[0], a1 = sA[1], a2 = sA[2];
        float4 b0 = sB[0], b1 = sB[1], b2 = sB[2];
        float4 c0 = sC[0], c1 = sC[1], c2 = sC[2];
        float4 d0 = sD[0], d1 = sD[1], d2 = sD[2];
        float4 xa0 = xA[0], xa1 = xA[1];
        float4 xb0 = xB[0], xb1 = xB[1];
        float4 xc0 = xC[0], xc1 = xC[1];
        float4 xd0 = xD[0], xd1 = xD[1];
        accum(a0, a1, a2, xa0, xa1, ar, ai);
        accum(b0, b1, b2, xb0, xb1, ar, ai);
        accum(c0, c1, c2, xc0, xc1, ar, ai);
        accum(d0, d1, d2, xd0, xd1, ar, ai);
    }
    for (; i < end; i++) {
        int2 p0 = g_pp[i];
        const float4* sA = (const float4*)(sten + (size_t)p0.y * 12);
        float4 a0 = sA[0], a1 = sA[1], a2 = sA[2];
        const float4* xA = (const float4*)(x + (size_t)p0.x * CIN);
        accum(a0, a1, a2, xA[0], xA[1], ar, ai);
    }

    // y[o] = sum_c phase[c,o] * (sum_r agg[r,c] * w[r,c,o]); magnitude gate
    float2* o2 = (float2*)out;
#pragma unroll 4
    for (int o = 0; o < COUT; o++) {
        float yr = 0.f, yi = 0.f;
#pragma unroll
        for (int c = 0; c < CIN; c++) {
            float tr = 0.f, ti = 0.f;
#pragma unroll
            for (int r = 0; r < RR; r++) {
                float w = sw[(r * CIN + c) * COUT + o];
                tr += ar[r * CIN + c] * w;
                ti += ai[r * CIN + c] * w;
            }
            float2 ph = sp[c * COUT + o];
            yr += tr * ph.x - ti * ph.y;
            yi += tr * ph.y + ti * ph.x;
        }
        float mag = sqrtf(yr * yr + yi * yi);
        float sc = fmaxf(mag + sb[o], 0.f) / (mag + 1e-8f);
        o2[(size_t)n * COUT + o] = make_float2(yr * sc, yi * sc);
    }
}

extern "C" void kernel_launch(void* const* d_in, const int* in_sizes, int n_in,
                              void* d_out, int out_size) {
    const float* x      = (const float*)d_in[0];
    const char*  edges  = (const char*)d_in[1];
    const float* sten   = (const float*)d_in[2];
    const float* weight = (const float*)d_in[3];
    const float* offset = (const float*)d_in[4];
    const float* bias   = (const float*)d_in[5];
    float*       out    = (float*)d_out;

    int E = in_sizes[1] / 2;
    int n = in_sizes[0] / CIN;

    k_init<<<(n + 255) / 256, 256>>>(offset, (const unsigned int*)edges, n);
    k_hist<<<(E + 255) / 256, 256>>>(edges, E);
    int nb = (n + CHUNK - 1) / CHUNK;
    k_scan1<<<nb, 256>>>(n);
    k_scan2<<<(n + 255) / 256, 256>>>(n, E, nb);
    k_scatter<<<(E + 255) / 256, 256>>>(E);
    k_node<<<(n + 127) / 128, 128>>>(x, sten, weight, bias, out, n);
}